// round 15
// baseline (speedup 1.0000x reference)
#include <cuda_runtime.h>
#include <cuda_fp16.h>

#define DM    1024
#define HH    16
#define DK    64
#define BB    2
#define LL    2048
#define NROWS (BB*LL)        /* 4096 */
#define DFF   4096
#define EPSLN 1e-5f
#define HEADS (BB*HH)

typedef __half fp16;

// scale for Q: 1/sqrt(64) * log2(e) so softmax can use exp2
#define QSCL 0.18033688011112042f

// ---------------- scratch (device globals; no allocations allowed) ----------
__device__ fp16  g_x16[(size_t)NROWS * DM];
__device__ fp16  g_Wqkv[3072ULL * 1024];      // [n=3072][k=1024]
__device__ fp16  g_Wo16[1024ULL * 1024];      // [n][k]
__device__ fp16  g_W116[4096ULL * 1024];      // [n=4096][k=1024]
__device__ fp16  g_W216[1024ULL * 4096];      // [n=1024][k=4096]
__device__ float g_bqkv[3072];
__device__ fp16  g_Qb[(size_t)HEADS * LL * DK];   // [bh][l][dk], pre-scaled
__device__ fp16  g_Kb[(size_t)HEADS * LL * DK];   // [bh][l][dk]
__device__ fp16  g_Vb[(size_t)HEADS * LL * DK];   // [bh][l][dv]  (row-major)
__device__ fp16  g_O16[(size_t)NROWS * DM];
__device__ float g_y1[(size_t)NROWS * DM];
__device__ float g_h1[(size_t)NROWS * DM];
__device__ fp16  g_h116[(size_t)NROWS * DM];
__device__ fp16  g_ff16[(size_t)NROWS * DFF];
__device__ float g_y2[(size_t)NROWS * DM];

__device__ __forceinline__ void mma16816(float* d, const unsigned* a,
                                         unsigned b0, unsigned b1) {
    asm volatile(
        "mma.sync.aligned.m16n8k16.row.col.f32.f16.f16.f32 "
        "{%0,%1,%2,%3}, {%4,%5,%6,%7}, {%8,%9}, {%0,%1,%2,%3};"
        : "+f"(d[0]), "+f"(d[1]), "+f"(d[2]), "+f"(d[3])
        : "r"(a[0]), "r"(a[1]), "r"(a[2]), "r"(a[3]), "r"(b0), "r"(b1));
}
__device__ __forceinline__ unsigned smem_u32(const void* p) {
    unsigned a;
    asm("{ .reg .u64 t; cvta.to.shared.u64 t, %1; cvt.u32.u64 %0, t; }"
        : "=r"(a) : "l"(p));
    return a;
}
__device__ __forceinline__ unsigned packh2(float lo, float hi) {
    unsigned r; asm("cvt.rn.f16x2.f32 %0, %1, %2;" : "=r"(r) : "f"(hi), "f"(lo));
    return r;
}
__device__ __forceinline__ unsigned h2ex2(unsigned x) {
    unsigned y; asm("ex2.approx.f16x2 %0, %1;" : "=r"(y) : "r"(x));
    return y;
}
__device__ __forceinline__ void ldmx4(unsigned& r0, unsigned& r1, unsigned& r2,
                                      unsigned& r3, unsigned addr) {
    asm volatile("ldmatrix.sync.aligned.m8n8.x4.shared.b16 {%0,%1,%2,%3}, [%4];"
                 : "=r"(r0), "=r"(r1), "=r"(r2), "=r"(r3) : "r"(addr));
}
__device__ __forceinline__ void ldmx4t(unsigned& r0, unsigned& r1, unsigned& r2,
                                       unsigned& r3, unsigned addr) {
    asm volatile("ldmatrix.sync.aligned.m8n8.x4.trans.shared.b16 {%0,%1,%2,%3}, [%4];"
                 : "=r"(r0), "=r"(r1), "=r"(r2), "=r"(r3) : "r"(addr));
}
__device__ __forceinline__ void cp16(unsigned dst, const void* src) {
    asm volatile("cp.async.cg.shared.global [%0], [%1], 16;" :: "r"(dst), "l"(src));
}
__device__ __forceinline__ void cp_commit() {
    asm volatile("cp.async.commit_group;" ::: "memory");
}
template <int N>
__device__ __forceinline__ void cp_wait() {
    asm volatile("cp.async.wait_group %0;" :: "n"(N) : "memory");
}
// ---- bulk-copy machinery (base sm_90 PTX, no arch-specific suffix) ----------
__device__ __forceinline__ void mbar_init(unsigned a, unsigned c) {
    asm volatile("mbarrier.init.shared.b64 [%0], %1;" :: "r"(a), "r"(c) : "memory");
}
__device__ __forceinline__ void mbar_expect(unsigned a, unsigned bytes) {
    asm volatile("mbarrier.arrive.expect_tx.shared.b64 _, [%0], %1;"
                 :: "r"(a), "r"(bytes) : "memory");
}
__device__ __forceinline__ void mbar_wait(unsigned a, unsigned ph) {
    unsigned done = 0;
    while (!done) {
        asm volatile(
            "{ .reg .pred p; mbarrier.try_wait.parity.acquire.cta.shared::cta.b64 p, [%1], %2;"
            " selp.b32 %0, 1, 0, p; }"
            : "=r"(done) : "r"(a), "r"(ph) : "memory");
    }
}
__device__ __forceinline__ void bulk128(unsigned dst, const void* src, unsigned mbar) {
    asm volatile(
        "cp.async.bulk.shared::cluster.global.mbarrier::complete_tx::bytes "
        "[%0], [%1], %2, [%3];"
        :: "r"(dst), "l"(src), "r"(128u), "r"(mbar) : "memory");
}
__device__ __forceinline__ void fence_async() {
    asm volatile("fence.proxy.async.shared::cta;" ::: "memory");
}

// ---------------- fused prep kernel (vectorized transposes) ------------------
#define PREP_BLOCKS 8204

__device__ __forceinline__ void tblock64v(
    const float* __restrict__ src, int srcStride, int scol,
    fp16* __restrict__ dst, int dstStride, int drow, int kb,
    float (*t)[65], int tid)
{
    {
        int r = tid >> 3, c0 = (tid & 7) * 8;
        const float* sp = src + (size_t)(kb + r) * srcStride + scol + c0;
        float4 f0 = *(const float4*)sp;
        float4 f1 = *(const float4*)(sp + 4);
        t[r][c0 + 0] = f0.x; t[r][c0 + 1] = f0.y;
        t[r][c0 + 2] = f0.z; t[r][c0 + 3] = f0.w;
        t[r][c0 + 4] = f1.x; t[r][c0 + 5] = f1.y;
        t[r][c0 + 6] = f1.z; t[r][c0 + 7] = f1.w;
    }
    __syncthreads();
    {
        int n = tid >> 2, k0 = (tid & 3) * 8;
        __half2 h[4];
        #pragma unroll
        for (int j = 0; j < 4; j++)
            h[j] = __floats2half2_rn(t[k0 + 2 * j][n], t[k0 + 2 * j + 1][n]);
        *(uint4*)(dst + (size_t)(drow + n) * dstStride + kb + k0) = *(uint4*)h;
    }
}

__global__ __launch_bounds__(256) void prep_kernel(
    const float* __restrict__ x,
    const float* __restrict__ Wq, const float* __restrict__ Wk,
    const float* __restrict__ Wv,
    const float* __restrict__ bq, const float* __restrict__ bk,
    const float* __restrict__ bv,
    const float* __restrict__ Wo, const float* __restrict__ W1,
    const float* __restrict__ W2)
{
    __shared__ float t[32][65];
    const int blk = blockIdx.x, tid = threadIdx.x;

    if (blk < 2048) {
        size_t base = (size_t)blk * 2048 + tid * 8;
        float4 f0 = *(const float4*)(x + base);
        float4 f1 = *(const float4*)(x + base + 4);
        __half2 h[4];
        h[0] = __floats2half2_rn(f0.x, f0.y);
        h[1] = __floats2half2_rn(f0.z, f0.w);
        h[2] = __floats2half2_rn(f1.x, f1.y);
        h[3] = __floats2half2_rn(f1.z, f1.w);
        *(uint4*)(g_x16 + base) = *(uint4*)h;
    } else if (blk < 2060) {
        int i = (blk - 2048) * 256 + tid;
        int z = i >> 10, idx = i & 1023;
        const float* s = (z == 0) ? bq : (z == 1) ? bk : bv;
        g_bqkv[i] = s[idx];
    } else if (blk < 3596) {
        int p = blk - 2060;
        int zh = p >> 5, kb = (p & 31) * 32;
        int z = zh >> 4, h = zh & 15;
        const float* src = ((z == 0) ? Wq : (z == 1) ? Wk : Wv) + (size_t)h * DM * DK;
        tblock64v(src, 64, 0, g_Wqkv, 1024, z * 1024 + h * 64, kb, t, tid);
    } else if (blk < 4108) {
        int p = blk - 3596;
        tblock64v(Wo, 1024, (p & 15) * 64, g_Wo16, 1024, (p & 15) * 64,
                  (p >> 4) * 32, t, tid);
    } else if (blk < 6156) {
        int p = blk - 4108;
        tblock64v(W1, 4096, (p & 63) * 64, g_W116, 1024, (p & 63) * 64,
                  (p >> 6) * 32, t, tid);
    } else {
        int p = blk - 6156;
        tblock64v(W2, 1024, (p & 15) * 64, g_W216, 4096, (p & 15) * 64,
                  (p >> 4) * 32, t, tid);
    }
}

// ---------------- fp16 mma.sync GEMM: bulk-copy staging ----------------------
#define GST 72                         /* smem row stride (fp16) */
#define A_H (128 * GST)                /* A tile halves */

template <int BN>
struct GCfg {
    static const int STAGE_H = (128 + BN) * GST;
    static const int ROWS = 128 + BN;              /* bulk copies per stage */
    static const unsigned STAGE_BYTES = ROWS * 128;
    static const int NTW = BN / 32;
    static const int NT8 = BN / 16;
    static const int SMEM = 3 * STAGE_H * 2;
};

template <int EPI, int BN>
__global__ __launch_bounds__(256) void gemm1_kernel(
    const fp16* __restrict__ A, const fp16* __restrict__ B,
    const float* __restrict__ bias, const float* __restrict__ res,
    float* __restrict__ outf, fp16* __restrict__ outh,
    int K, int N)
{
    typedef GCfg<BN> C;
    extern __shared__ fp16 smem[];
    __shared__ __align__(8) unsigned long long s_mbar[3];
    const int tid = threadIdx.x;
    const int lane = tid & 31, wid = tid >> 5;
    const int wm = wid & 3, wn = wid >> 2;       // 4 x 2 warp grid
    const int g = lane >> 2, l2 = (lane & 3) * 2;
    const int m0 = blockIdx.y * 128, n0 = blockIdx.x * BN;
    const int nk = K >> 6;
    const unsigned smb = smem_u32(smem);
    const unsigned mbb = smem_u32(&s_mbar[0]);

    const int lrow = lane & 7;
    const int arow = lrow + ((lane >> 3) & 1) * 8;
    const int acol = (lane >> 4) << 3;
    const int brow = lrow + ((lane >> 4) << 3);
    const int bcol = ((lane >> 3) & 1) << 3;

    if (tid == 0) {
        mbar_init(mbb, 1);
        mbar_init(mbb + 8, 1);
        mbar_init(mbb + 16, 1);
        fence_async();
    }
    __syncthreads();

    float d[2][C::NT8][4] = {};

#define G_ISSUE(KS) do {                                                     \
        const int _k0 = (KS) << 6;                                           \
        unsigned _sb = smb + ((KS) % 3) * (C::STAGE_H * 2);                  \
        unsigned _mb = mbb + ((KS) % 3) * 8;                                 \
        if (tid == 0) mbar_expect(_mb, C::STAGE_BYTES);                      \
        if (tid < C::ROWS) {                                                 \
            const fp16* _src = (tid < 128)                                   \
                ? A + (size_t)(m0 + tid) * K + _k0                           \
                : B + (size_t)(n0 + tid - 128) * K + _k0;                    \
            bulk128(_sb + tid * (GST * 2), _src, _mb);                       \
        }                                                                    \
    } while (0)

    G_ISSUE(0);
    G_ISSUE(1);

    for (int ks = 0; ks < nk; ks++) {
        mbar_wait(mbb + (ks % 3) * 8, (unsigned)(ks / 3) & 1u);
        __syncthreads();
        if (ks + 2 < nk) G_ISSUE(ks + 2);

        const unsigned sA = smb + (ks % 3) * (C::STAGE_H * 2);
        const unsigned sB = sA + A_H * 2;

        #pragma unroll
        for (int kk = 0; kk < 4; kk++) {
            unsigned a[2][4];
            #pragma unroll
            for (int mt = 0; mt < 2; mt++) {
                unsigned aoff = (((wm * 32 + mt * 16 + arow) * GST) + kk * 16 + acol) * 2;
                ldmx4(a[mt][0], a[mt][1], a[mt][2], a[mt][3], sA + aoff);
            }
            #pragma unroll
            for (int nt2 = 0; nt2 < C::NTW; nt2++) {
                unsigned boff = (((wn * (BN / 2) + nt2 * 16 + brow) * GST) +
                                 kk * 16 + bcol) * 2;
                unsigned b0, b1, b2, b3;
                ldmx4(b0, b1, b2, b3, sB + boff);
                #pragma unroll
                for (int mt = 0; mt < 2; mt++) {
                    mma16816(d[mt][2 * nt2],     a[mt], b0, b1);
                    mma16816(d[mt][2 * nt2 + 1], a[mt], b2, b3);
                }
            }
        }
    }
#undef G_ISSUE

    #pragma unroll
    for (int mt = 0; mt < 2; mt++) {
        #pragma unroll
        for (int nt = 0; nt < C::NT8; nt++) {
            int rbase = m0 + wm * 32 + mt * 16 + g;
            int cc = n0 + wn * (BN / 2) + nt * 8 + l2;
            #pragma unroll
            for (int rr = 0; rr < 2; rr++) {
                int rg = rbase + rr * 8;
                float v0 = d[mt][nt][rr * 2 + 0];
                float v1 = d[mt][nt][rr * 2 + 1];
                if (EPI == 0) {
                    float2 bv = *(const float2*)(bias + cc);
                    float w0 = v0 + bv.x, w1 = v1 + bv.y;
                    int z = cc >> 10, h = (cc >> 6) & 15, dk = cc & 63;
                    int bb_ = rg >> 11, lpos = rg & 2047;
                    size_t o = ((size_t)(bb_ * 16 + h) * 2048 + lpos) * 64 + dk;
                    if (z == 0) {
                        w0 *= QSCL; w1 *= QSCL;
                        *(__half2*)(g_Qb + o) =
                            __halves2half2(__float2half_rn(w0), __float2half_rn(w1));
                    } else if (z == 1) {
                        *(__half2*)(g_Kb + o) =
                            __halves2half2(__float2half_rn(w0), __float2half_rn(w1));
                    } else {
                        *(__half2*)(g_Vb + o) =
                            __halves2half2(__float2half_rn(w0), __float2half_rn(w1));
                    }
                } else if (EPI == 1) {
                    size_t o = (size_t)rg * N + cc;
                    float2 rv = *(const float2*)(res + o);
                    *(float2*)(outf + o) = make_float2(v0 + rv.x, v1 + rv.y);
                } else {
                    size_t o = (size_t)rg * N + cc;
                    float2 bv = *(const float2*)(bias + cc);
                    float w0 = fmaxf(v0 + bv.x, 0.f);
                    float w1 = fmaxf(v1 + bv.y, 0.f);
                    *(__half2*)(outh + o) =
                        __halves2half2(__float2half_rn(w0), __float2half_rn(w1));
                }
            }
        }
    }
}

// ---------------- fp16 flash attention (R14, frozen) -------------------------
#define KST 72
#define VST 88
#define QS_SZ   (256 * KST)
#define KT_SZ   (128 * KST)
#define VT_SZ   (128 * VST)
#define BUF_H   (KT_SZ + VT_SZ)
#define BUF_BYTES (BUF_H * 2)
#define ATTN_SMEM (QS_SZ * 2 + 3 * BUF_BYTES)

__global__ __launch_bounds__(256) void attn_kernel()
{
    extern __shared__ fp16 sm[];
    fp16* Qs = sm;
    const int tid = threadIdx.x, lane = tid & 31, w = tid >> 5;
    const int g = lane >> 2, t = lane & 3;
    const int qt = blockIdx.x, bh = blockIdx.y;
    const int bI = bh >> 4, h = bh & 15;

    const fp16* Qg = g_Qb + ((size_t)bh * LL + qt * 256) * 64;
    const fp16* Kg = g_Kb + (size_t)bh * LL * 64;
    const fp16* Vg = g_Vb + (size_t)bh * LL * 64;
    const unsigned smb = smem_u32(sm);

#define A_ISSUE(KT) do {                                                       \
        unsigned _kbase = smb + QS_SZ * 2 + ((KT) % 3) * BUF_BYTES;            \
        unsigned _vbase = _kbase + KT_SZ * 2;                                  \
        const fp16* _Kp = Kg + (size_t)(KT) * 128 * 64;                        \
        const fp16* _Vp = Vg + (size_t)(KT) * 128 * 64;                        \
        _Pragma("unroll")                                                      \
        for (int _i = 0; _i < 4; _i++) {                                       \
            int _c = tid + _i * 256;                                           \
            int _r = _c >> 3, _cc = (_c & 7) * 8;                              \
            cp16(_kbase + (_r * KST + _cc) * 2, _Kp + _r * 64 + _cc);          \
            cp16(_vbase + (_r * VST + _cc) * 2, _Vp + _r * 64 + _cc);          \
        }                                                                      \
        cp_commit();                                                           \
    } while (0)

    #pragma unroll
    for (int i = 0; i < 8; i++) {
        int c = tid + i * 256;
        int r = c >> 3, cc = (c & 7) * 8;
        *(uint4*)(Qs + r * KST + cc) = *(const uint4*)(Qg + r * 64 + cc);
    }
    {
        const __half2 one0 = __halves2half2(__float2half_rn(1.f), __float2half_rn(0.f));
        const __half2 zz   = __halves2half2(__float2half_rn(0.f), __float2half_rn(0.f));
        __half2 v0[4] = {one0, zz, zz, zz};
        __half2 v1[4] = {zz, zz, zz, zz};
        for (int i = tid; i < 3 * 128; i += 256) {
            int buf = i >> 7, r = i & 127;
            fp16* vp = sm + QS_SZ + buf * BUF_H + KT_SZ + r * VST + 64;
            *(uint4*)vp = *(uint4*)v0;
            *(uint4*)(vp + 8) = *(uint4*)v1;
        }
    }
    A_ISSUE(0);
    A_ISSUE(1);
    __syncthreads();

    unsigned qa[2][4][4];
    #pragma unroll
    for (int hq = 0; hq < 2; hq++) {
        const int qrow = hq * 128 + w * 16 + g;
        #pragma unroll
        for (int kk = 0; kk < 4; kk++) {
            qa[hq][kk][0] = *(const unsigned*)(Qs + qrow * KST + kk * 16 + 2 * t);
            qa[hq][kk][1] = *(const unsigned*)(Qs + (qrow + 8) * KST + kk * 16 + 2 * t);
            qa[hq][kk][2] = *(const unsigned*)(Qs + qrow * KST + kk * 16 + 8 + 2 * t);
            qa[hq][kk][3] = *(const unsigned*)(Qs + (qrow + 8) * KST + kk * 16 + 8 + 2 * t);
        }
    }

    float o[2][8][4] = {};
    float ol[2][4] = {};

    const int lrow = lane & 7;
    const int lh8  = ((lane >> 3) & 1) << 3;
    const int ln8  = (lane >> 4) << 3;
    const int vrow = lrow + lh8;
    const int vcol = ln8;

    for (int kt = 0; kt < 16; kt++) {
        if (kt + 1 < 16) cp_wait<1>(); else cp_wait<0>();
        __syncthreads();
        if (kt + 2 < 16) A_ISSUE(kt + 2);

        const unsigned Kb_ = smb + QS_SZ * 2 + (kt % 3) * BUF_BYTES;
        const unsigned Vb_ = Kb_ + KT_SZ * 2;

        #pragma unroll
        for (int hq = 0; hq < 2; hq++) {
            float s[16][4] = {};
            #pragma unroll
            for (int kk = 0; kk < 4; kk++) {
                #pragma unroll
                for (int nt2 = 0; nt2 < 8; nt2++) {
                    unsigned r0, r1, r2, r3;
                    unsigned addr = Kb_ +
                        (((nt2 * 16 + lrow + ln8) * KST) + kk * 16 + lh8) * 2;
                    ldmx4(r0, r1, r2, r3, addr);
                    mma16816(s[2 * nt2],     qa[hq][kk], r0, r1);
                    mma16816(s[2 * nt2 + 1], qa[hq][kk], r2, r3);
                }
            }

            unsigned aP[8][4];
            #pragma unroll
            for (int nt = 0; nt < 16; nt++) {
                unsigned sp01 = packh2(s[nt][0], s[nt][1]);
                unsigned sp23 = packh2(s[nt][2], s[nt][3]);
                int k2 = nt >> 1, off = (nt & 1) * 2;
                aP[k2][off]     = h2ex2(sp01);
                aP[k2][off + 1] = h2ex2(sp23);
            }

            #pragma unroll
            for (int kt2 = 0; kt2 < 8; kt2++) {
                #pragma unroll
                for (int nt2 = 0; nt2 < 4; nt2++) {
                    unsigned r0, r1, r2, r3;
                    unsigned addr = Vb_ +
                        (((kt2 * 16 + vrow) * VST) + nt2 * 16 + vcol) * 2;
                    ldmx4t(r0, r1, r2, r3, addr);
                    mma16816(o[hq][2 * nt2],     aP[kt2], r0, r1);
                    mma16816(o[hq][2 * nt2 + 1], aP[kt2], r2, r3);
                }
                unsigned r0, r1, r2, r3;
                unsigned addr = Vb_ +
                    (((kt2 * 16 + vrow) * VST) + 64 + vcol) * 2;
                ldmx4t(r0, r1, r2, r3, addr);
                mma16816(ol[hq], aP[kt2], r0, r1);
            }
        }
    }
#undef A_ISSUE

    #pragma unroll
    for (int hq = 0; hq < 2; hq++) {
        int qlead = lane & ~3;
        float l0 = __shfl_sync(0xffffffffu, ol[hq][0], qlead);
        float l1 = __shfl_sync(0xffffffffu, ol[hq][2], qlead);
        float inv0 = 1.f / l0, inv1 = 1.f / l1;
        size_t row0 = (size_t)bI * 2048 + qt * 256 + hq * 128 + w * 16 + g;
        #pragma unroll
        for (int nt = 0; nt < 8; nt++) {
            int col = h * 64 + nt * 8 + 2 * t;
            size_t o0 = row0 * DM + col;
            size_t o1 = (row0 + 8) * DM + col;
            *(__half2*)(g_O16 + o0) =
                __halves2half2(__float2half_rn(o[hq][nt][0] * inv0),
                               __float2half_rn(o[hq][nt][1] * inv0));
            *(__half2*)(g_O16 + o1) =
                __halves2half2(__float2half_rn(o[hq][nt][2] * inv1),
                               __float2half_rn(o[hq][nt][3] * inv1));
        }
    }
}

// ---------------- row LayerNorm (warp-shuffle reduction) ----------------------
template <bool EMIT16>
__global__ __launch_bounds__(256) void ln_kernel(
    const float* __restrict__ y, const float* __restrict__ g,
    const float* __restrict__ bta, float* __restrict__ out,
    fp16* __restrict__ outh)
{
    __shared__ float sa[8], sq[8];
    const int tid = threadIdx.x, lane = tid & 31, wrp = tid >> 5;
    const int row = blockIdx.x;
    const float* yr = y + (size_t)row * DM;
    float v[4];
    float a = 0.f, q = 0.f;
    #pragma unroll
    for (int i = 0; i < 4; i++) {
        v[i] = yr[tid + i * 256];
        a += v[i]; q += v[i] * v[i];
    }
    #pragma unroll
    for (int off = 16; off > 0; off >>= 1) {
        a += __shfl_xor_sync(0xffffffffu, a, off);
        q += __shfl_xor_sync(0xffffffffu, q, off);
    }
    if (lane == 0) { sa[wrp] = a; sq[wrp] = q; }
    __syncthreads();
    a = sa[0] + sa[1] + sa[2] + sa[3] + sa[4] + sa[5] + sa[6] + sa[7];
    q = sq[0] + sq[1] + sq[2] + sq[3] + sq[4] + sq[5] + sq[6] + sq[7];
    const float mu = a * (1.f / DM);
    const float var = q * (1.f / DM) - mu * mu;
    const float rstd = rsqrtf(var + EPSLN);
    #pragma unroll
    for (int i = 0; i < 4; i++) {
        int c = tid + i * 256;
        size_t o = (size_t)row * DM + c;
        float ov = (v[i] - mu) * rstd * g[c] + bta[c];
        out[o] = ov;
        if (EMIT16) outh[o] = __float2half_rn(ov);
    }
}

// ---------------- launch ------------------------------------------------------
extern "C" void kernel_launch(void* const* d_in, const int* in_sizes, int n_in,
                              void* d_out, int out_size)
{
    const float* x   = (const float*)d_in[0];
    const float* Wq  = (const float*)d_in[1];
    const float* bq  = (const float*)d_in[2];
    const float* Wk  = (const float*)d_in[3];
    const float* bk  = (const float*)d_in[4];
    const float* Wv  = (const float*)d_in[5];
    const float* bv  = (const float*)d_in[6];
    const float* Wo  = (const float*)d_in[7];
    const float* g1  = (const float*)d_in[8];
    const float* be1 = (const float*)d_in[9];
    const float* W1  = (const float*)d_in[10];
    const float* b1f = (const float*)d_in[11];
    const float* W2  = (const float*)d_in[12];
    const float* g2  = (const float*)d_in[13];
    const float* be2 = (const float*)d_in[14];
    float* out = (float*)d_out;

    void *px16, *pWq, *pWo, *pW1, *pW2, *pbq, *pO, *py1, *ph1, *ph116, *pff, *py2;
    cudaGetSymbolAddress(&px16, g_x16);
    cudaGetSymbolAddress(&pWq, g_Wqkv);
    cudaGetSymbolAddress(&pWo, g_Wo16);
    cudaGetSymbolAddress(&pW1, g_W116);
    cudaGetSymbolAddress(&pW2, g_W216);
    cudaGetSymbolAddress(&pbq, g_bqkv);
    cudaGetSymbolAddress(&pO, g_O16);
    cudaGetSymbolAddress(&py1, g_y1);
    cudaGetSymbolAddress(&ph1, g_h1);
    cudaGetSymbolAddress(&ph116, g_h116);
    cudaGetSymbolAddress(&pff, g_ff16);
    cudaGetSymbolAddress(&py2, g_y2);

    cudaFuncSetAttribute(gemm1_kernel<0, 96>,
                         cudaFuncAttributeMaxDynamicSharedMemorySize, GCfg<96>::SMEM);
    cudaFuncSetAttribute(gemm1_kernel<1, 128>,
                         cudaFuncAttributeMaxDynamicSharedMemorySize, GCfg<128>::SMEM);
    cudaFuncSetAttribute(gemm1_kernel<2, 128>,
                         cudaFuncAttributeMaxDynamicSharedMemorySize, GCfg<128>::SMEM);
    cudaFuncSetAttribute(attn_kernel,
                         cudaFuncAttributeMaxDynamicSharedMemorySize, ATTN_SMEM);

    // ---- prep (single fused launch)
    prep_kernel<<<PREP_BLOCKS, 256>>>(x, Wq, Wk, Wv, bq, bk, bv, Wo, W1, W2);

    // ---- 1) QKV projection (BN=96)
    gemm1_kernel<0, 96><<<dim3(32, 32), 256, GCfg<96>::SMEM>>>(
        (const fp16*)px16, (const fp16*)pWq, (const float*)pbq,
        nullptr, nullptr, nullptr, 1024, 3072);

    // ---- 2) tensor-core flash attention
    attn_kernel<<<dim3(8, HEADS), 256, ATTN_SMEM>>>();

    // ---- 3) O-proj + residual x -> y1
    gemm1_kernel<1, 128><<<dim3(8, 32), 256, GCfg<128>::SMEM>>>(
        (const fp16*)pO, (const fp16*)pWo, nullptr, x, (float*)py1, nullptr,
        1024, 1024);

    // ---- 4) LayerNorm 1
    ln_kernel<true><<<NROWS, 256>>>((const float*)py1, g1, be1,
                                    (float*)ph1, (fp16*)ph116);

    // ---- 5) FFN up + bias + ReLU
    gemm1_kernel<2, 128><<<dim3(32, 32), 256, GCfg<128>::SMEM>>>(
        (const fp16*)ph116, (const fp16*)pW1, b1f, nullptr, nullptr, (fp16*)pff,
        1024, 4096);

    // ---- 6) FFN down + residual h1 -> y2
    gemm1_kernel<1, 128><<<dim3(8, 32), 256, GCfg<128>::SMEM>>>(
        (const fp16*)pff, (const fp16*)pW2, nullptr, (const float*)ph1,
        (float*)py2, nullptr, 4096, 1024);

    // ---- 7) LayerNorm 2 -> output
    ln_kernel<false><<<NROWS, 256>>>((const float*)py2, g2, be2, out, nullptr);
}

// round 16
// speedup vs baseline: 1.1355x; 1.1355x over previous
#include <cuda_runtime.h>
#include <cuda_fp16.h>

#define DM    1024
#define HH    16
#define DK    64
#define BB    2
#define LL    2048
#define NROWS (BB*LL)        /* 4096 */
#define DFF   4096
#define EPSLN 1e-5f
#define HEADS (BB*HH)

typedef __half fp16;

// scale for Q: 1/sqrt(64) * log2(e) so softmax can use exp2
#define QSCL 0.18033688011112042f

// ---------------- scratch (device globals; no allocations allowed) ----------
__device__ fp16  g_x16[(size_t)NROWS * DM];
__device__ fp16  g_Wqkv[3072ULL * 1024];      // [n=3072][k=1024]
__device__ fp16  g_Wo16[1024ULL * 1024];      // [n][k]
__device__ fp16  g_W116[4096ULL * 1024];      // [n=4096][k=1024]
__device__ fp16  g_W216[1024ULL * 4096];      // [n=1024][k=4096]
__device__ float g_bqkv[3072];
__device__ fp16  g_Qb[(size_t)HEADS * LL * DK];   // [bh][l][dk], pre-scaled
__device__ fp16  g_Kb[(size_t)HEADS * LL * DK];   // [bh][l][dk]
__device__ fp16  g_Vb[(size_t)HEADS * LL * DK];   // [bh][l][dv]  (row-major)
__device__ fp16  g_O16[(size_t)NROWS * DM];
__device__ float g_y1[(size_t)NROWS * DM];
__device__ float g_h1[(size_t)NROWS * DM];
__device__ fp16  g_h116[(size_t)NROWS * DM];
__device__ fp16  g_ff16[(size_t)NROWS * DFF];
__device__ float g_y2[(size_t)NROWS * DM];

__device__ __forceinline__ void mma16816(float* d, const unsigned* a,
                                         unsigned b0, unsigned b1) {
    asm volatile(
        "mma.sync.aligned.m16n8k16.row.col.f32.f16.f16.f32 "
        "{%0,%1,%2,%3}, {%4,%5,%6,%7}, {%8,%9}, {%0,%1,%2,%3};"
        : "+f"(d[0]), "+f"(d[1]), "+f"(d[2]), "+f"(d[3])
        : "r"(a[0]), "r"(a[1]), "r"(a[2]), "r"(a[3]), "r"(b0), "r"(b1));
}
__device__ __forceinline__ unsigned smem_u32(const void* p) {
    unsigned a;
    asm("{ .reg .u64 t; cvta.to.shared.u64 t, %1; cvt.u32.u64 %0, t; }"
        : "=r"(a) : "l"(p));
    return a;
}
__device__ __forceinline__ unsigned packh2(float lo, float hi) {
    unsigned r; asm("cvt.rn.f16x2.f32 %0, %1, %2;" : "=r"(r) : "f"(hi), "f"(lo));
    return r;
}
__device__ __forceinline__ unsigned h2ex2(unsigned x) {
    unsigned y; asm("ex2.approx.f16x2 %0, %1;" : "=r"(y) : "r"(x));
    return y;
}
__device__ __forceinline__ void ldmx4(unsigned& r0, unsigned& r1, unsigned& r2,
                                      unsigned& r3, unsigned addr) {
    asm volatile("ldmatrix.sync.aligned.m8n8.x4.shared.b16 {%0,%1,%2,%3}, [%4];"
                 : "=r"(r0), "=r"(r1), "=r"(r2), "=r"(r3) : "r"(addr));
}
__device__ __forceinline__ void ldmx4t(unsigned& r0, unsigned& r1, unsigned& r2,
                                       unsigned& r3, unsigned addr) {
    asm volatile("ldmatrix.sync.aligned.m8n8.x4.trans.shared.b16 {%0,%1,%2,%3}, [%4];"
                 : "=r"(r0), "=r"(r1), "=r"(r2), "=r"(r3) : "r"(addr));
}
__device__ __forceinline__ void cp16(unsigned dst, const void* src) {
    asm volatile("cp.async.cg.shared.global [%0], [%1], 16;" :: "r"(dst), "l"(src));
}
__device__ __forceinline__ void cp_commit() {
    asm volatile("cp.async.commit_group;" ::: "memory");
}
template <int N>
__device__ __forceinline__ void cp_wait() {
    asm volatile("cp.async.wait_group %0;" :: "n"(N) : "memory");
}

// ---------------- fused prep kernel (vectorized transposes) ------------------
#define PREP_BLOCKS 8204

__device__ __forceinline__ void tblock64v(
    const float* __restrict__ src, int srcStride, int scol,
    fp16* __restrict__ dst, int dstStride, int drow, int kb,
    float (*t)[65], int tid)
{
    {
        int r = tid >> 3, c0 = (tid & 7) * 8;
        const float* sp = src + (size_t)(kb + r) * srcStride + scol + c0;
        float4 f0 = *(const float4*)sp;
        float4 f1 = *(const float4*)(sp + 4);
        t[r][c0 + 0] = f0.x; t[r][c0 + 1] = f0.y;
        t[r][c0 + 2] = f0.z; t[r][c0 + 3] = f0.w;
        t[r][c0 + 4] = f1.x; t[r][c0 + 5] = f1.y;
        t[r][c0 + 6] = f1.z; t[r][c0 + 7] = f1.w;
    }
    __syncthreads();
    {
        int n = tid >> 2, k0 = (tid & 3) * 8;
        __half2 h[4];
        #pragma unroll
        for (int j = 0; j < 4; j++)
            h[j] = __floats2half2_rn(t[k0 + 2 * j][n], t[k0 + 2 * j + 1][n]);
        *(uint4*)(dst + (size_t)(drow + n) * dstStride + kb + k0) = *(uint4*)h;
    }
}

__global__ __launch_bounds__(256) void prep_kernel(
    const float* __restrict__ x,
    const float* __restrict__ Wq, const float* __restrict__ Wk,
    const float* __restrict__ Wv,
    const float* __restrict__ bq, const float* __restrict__ bk,
    const float* __restrict__ bv,
    const float* __restrict__ Wo, const float* __restrict__ W1,
    const float* __restrict__ W2)
{
    __shared__ float t[32][65];
    const int blk = blockIdx.x, tid = threadIdx.x;

    if (blk < 2048) {
        size_t base = (size_t)blk * 2048 + tid * 8;
        float4 f0 = *(const float4*)(x + base);
        float4 f1 = *(const float4*)(x + base + 4);
        __half2 h[4];
        h[0] = __floats2half2_rn(f0.x, f0.y);
        h[1] = __floats2half2_rn(f0.z, f0.w);
        h[2] = __floats2half2_rn(f1.x, f1.y);
        h[3] = __floats2half2_rn(f1.z, f1.w);
        *(uint4*)(g_x16 + base) = *(uint4*)h;
    } else if (blk < 2060) {
        int i = (blk - 2048) * 256 + tid;
        int z = i >> 10, idx = i & 1023;
        const float* s = (z == 0) ? bq : (z == 1) ? bk : bv;
        g_bqkv[i] = s[idx];
    } else if (blk < 3596) {
        int p = blk - 2060;
        int zh = p >> 5, kb = (p & 31) * 32;
        int z = zh >> 4, h = zh & 15;
        const float* src = ((z == 0) ? Wq : (z == 1) ? Wk : Wv) + (size_t)h * DM * DK;
        tblock64v(src, 64, 0, g_Wqkv, 1024, z * 1024 + h * 64, kb, t, tid);
    } else if (blk < 4108) {
        int p = blk - 3596;
        tblock64v(Wo, 1024, (p & 15) * 64, g_Wo16, 1024, (p & 15) * 64,
                  (p >> 4) * 32, t, tid);
    } else if (blk < 6156) {
        int p = blk - 4108;
        tblock64v(W1, 4096, (p & 63) * 64, g_W116, 1024, (p & 63) * 64,
                  (p >> 6) * 32, t, tid);
    } else {
        int p = blk - 6156;
        tblock64v(W2, 1024, (p & 15) * 64, g_W216, 4096, (p & 15) * 64,
                  (p >> 4) * 32, t, tid);
    }
}

// ---------------- fp16 mma.sync GEMM (R14 config: cp.async, 3-stage) ---------
#define GST 72                         /* smem row stride (fp16) */
#define A_H (128 * GST)                /* A tile halves */

template <int BN>
struct GCfg {
    static const int STAGE_H = (128 + BN) * GST;
    static const int NITER = (1024 + 8 * BN) / 256;  /* cp16 per thread */
    static const int NTW = BN / 32;
    static const int NT8 = BN / 16;
    static const int SMEM = 3 * STAGE_H * 2;
};

template <int EPI, int BN>
__global__ __launch_bounds__(256) void gemm1_kernel(
    const fp16* __restrict__ A, const fp16* __restrict__ B,
    const float* __restrict__ bias, const float* __restrict__ res,
    float* __restrict__ outf, fp16* __restrict__ outh,
    int K, int N)
{
    typedef GCfg<BN> C;
    extern __shared__ fp16 smem[];
    const int tid = threadIdx.x;
    const int lane = tid & 31, wid = tid >> 5;
    const int wm = wid & 3, wn = wid >> 2;       // 4 x 2 warp grid
    const int g = lane >> 2, l2 = (lane & 3) * 2;
    const int m0 = blockIdx.y * 128, n0 = blockIdx.x * BN;
    const int nk = K >> 6;
    const unsigned smb = smem_u32(smem);

    const int lrow = lane & 7;
    const int arow = lrow + ((lane >> 3) & 1) * 8;
    const int acol = (lane >> 4) << 3;
    const int brow = lrow + ((lane >> 4) << 3);
    const int bcol = ((lane >> 3) & 1) << 3;

    float d[2][C::NT8][4] = {};

#define G_ISSUE(KS) do {                                                     \
        const int _k0 = (KS) << 6;                                           \
        unsigned _sb = smb + ((KS) % 3) * (C::STAGE_H * 2);                  \
        _Pragma("unroll")                                                    \
        for (int _i = 0; _i < C::NITER; _i++) {                              \
            int _idx = tid + _i * 256;                                       \
            if (_idx < 1024) {                                               \
                int _r = _idx >> 3, _c = (_idx & 7) * 8;                     \
                cp16(_sb + (_r * GST + _c) * 2,                              \
                     A + (size_t)(m0 + _r) * K + _k0 + _c);                  \
            } else {                                                         \
                int _j = _idx - 1024;                                        \
                int _r = _j >> 3, _c = (_j & 7) * 8;                         \
                cp16(_sb + ((128 + _r) * GST + _c) * 2,                      \
                     B + (size_t)(n0 + _r) * K + _k0 + _c);                  \
            }                                                                \
        }                                                                    \
        cp_commit();                                                         \
    } while (0)

    G_ISSUE(0);
    G_ISSUE(1);

    for (int ks = 0; ks < nk; ks++) {
        if (ks + 1 < nk) cp_wait<1>(); else cp_wait<0>();
        __syncthreads();
        if (ks + 2 < nk) G_ISSUE(ks + 2);

        const unsigned sA = smb + (ks % 3) * (C::STAGE_H * 2);
        const unsigned sB = sA + A_H * 2;

        #pragma unroll
        for (int kk = 0; kk < 4; kk++) {
            unsigned a[2][4];
            #pragma unroll
            for (int mt = 0; mt < 2; mt++) {
                unsigned aoff = (((wm * 32 + mt * 16 + arow) * GST) + kk * 16 + acol) * 2;
                ldmx4(a[mt][0], a[mt][1], a[mt][2], a[mt][3], sA + aoff);
            }
            #pragma unroll
            for (int nt2 = 0; nt2 < C::NTW; nt2++) {
                unsigned boff = (((wn * (BN / 2) + nt2 * 16 + brow) * GST) +
                                 kk * 16 + bcol) * 2;
                unsigned b0, b1, b2, b3;
                ldmx4(b0, b1, b2, b3, sB + boff);
                #pragma unroll
                for (int mt = 0; mt < 2; mt++) {
                    mma16816(d[mt][2 * nt2],     a[mt], b0, b1);
                    mma16816(d[mt][2 * nt2 + 1], a[mt], b2, b3);
                }
            }
        }
    }
#undef G_ISSUE

    #pragma unroll
    for (int mt = 0; mt < 2; mt++) {
        #pragma unroll
        for (int nt = 0; nt < C::NT8; nt++) {
            int rbase = m0 + wm * 32 + mt * 16 + g;
            int cc = n0 + wn * (BN / 2) + nt * 8 + l2;
            #pragma unroll
            for (int rr = 0; rr < 2; rr++) {
                int rg = rbase + rr * 8;
                float v0 = d[mt][nt][rr * 2 + 0];
                float v1 = d[mt][nt][rr * 2 + 1];
                if (EPI == 0) {
                    float2 bv = *(const float2*)(bias + cc);
                    float w0 = v0 + bv.x, w1 = v1 + bv.y;
                    int z = cc >> 10, h = (cc >> 6) & 15, dk = cc & 63;
                    int bb_ = rg >> 11, lpos = rg & 2047;
                    size_t o = ((size_t)(bb_ * 16 + h) * 2048 + lpos) * 64 + dk;
                    if (z == 0) {
                        w0 *= QSCL; w1 *= QSCL;
                        *(__half2*)(g_Qb + o) =
                            __halves2half2(__float2half_rn(w0), __float2half_rn(w1));
                    } else if (z == 1) {
                        *(__half2*)(g_Kb + o) =
                            __halves2half2(__float2half_rn(w0), __float2half_rn(w1));
                    } else {
                        *(__half2*)(g_Vb + o) =
                            __halves2half2(__float2half_rn(w0), __float2half_rn(w1));
                    }
                } else if (EPI == 1) {
                    size_t o = (size_t)rg * N + cc;
                    float2 rv = *(const float2*)(res + o);
                    *(float2*)(outf + o) = make_float2(v0 + rv.x, v1 + rv.y);
                } else {
                    size_t o = (size_t)rg * N + cc;
                    float2 bv = *(const float2*)(bias + cc);
                    float w0 = fmaxf(v0 + bv.x, 0.f);
                    float w1 = fmaxf(v1 + bv.y, 0.f);
                    *(__half2*)(outh + o) =
                        __halves2half2(__float2half_rn(w0), __float2half_rn(w1));
                }
            }
        }
    }
}

// ---------------- fp16 flash attention (R14, frozen) -------------------------
#define KST 72
#define VST 88
#define QS_SZ   (256 * KST)
#define KT_SZ   (128 * KST)
#define VT_SZ   (128 * VST)
#define BUF_H   (KT_SZ + VT_SZ)
#define BUF_BYTES (BUF_H * 2)
#define ATTN_SMEM (QS_SZ * 2 + 3 * BUF_BYTES)

__global__ __launch_bounds__(256) void attn_kernel()
{
    extern __shared__ fp16 sm[];
    fp16* Qs = sm;
    const int tid = threadIdx.x, lane = tid & 31, w = tid >> 5;
    const int g = lane >> 2, t = lane & 3;
    const int qt = blockIdx.x, bh = blockIdx.y;
    const int bI = bh >> 4, h = bh & 15;

    const fp16* Qg = g_Qb + ((size_t)bh * LL + qt * 256) * 64;
    const fp16* Kg = g_Kb + (size_t)bh * LL * 64;
    const fp16* Vg = g_Vb + (size_t)bh * LL * 64;
    const unsigned smb = smem_u32(sm);

#define A_ISSUE(KT) do {                                                       \
        unsigned _kbase = smb + QS_SZ * 2 + ((KT) % 3) * BUF_BYTES;            \
        unsigned _vbase = _kbase + KT_SZ * 2;                                  \
        const fp16* _Kp = Kg + (size_t)(KT) * 128 * 64;                        \
        const fp16* _Vp = Vg + (size_t)(KT) * 128 * 64;                        \
        _Pragma("unroll")                                                      \
        for (int _i = 0; _i < 4; _i++) {                                       \
            int _c = tid + _i * 256;                                           \
            int _r = _c >> 3, _cc = (_c & 7) * 8;                              \
            cp16(_kbase + (_r * KST + _cc) * 2, _Kp + _r * 64 + _cc);          \
            cp16(_vbase + (_r * VST + _cc) * 2, _Vp + _r * 64 + _cc);          \
        }                                                                      \
        cp_commit();                                                           \
    } while (0)

    #pragma unroll
    for (int i = 0; i < 8; i++) {
        int c = tid + i * 256;
        int r = c >> 3, cc = (c & 7) * 8;
        *(uint4*)(Qs + r * KST + cc) = *(const uint4*)(Qg + r * 64 + cc);
    }
    {
        const __half2 one0 = __halves2half2(__float2half_rn(1.f), __float2half_rn(0.f));
        const __half2 zz   = __halves2half2(__float2half_rn(0.f), __float2half_rn(0.f));
        __half2 v0[4] = {one0, zz, zz, zz};
        __half2 v1[4] = {zz, zz, zz, zz};
        for (int i = tid; i < 3 * 128; i += 256) {
            int buf = i >> 7, r = i & 127;
            fp16* vp = sm + QS_SZ + buf * BUF_H + KT_SZ + r * VST + 64;
            *(uint4*)vp = *(uint4*)v0;
            *(uint4*)(vp + 8) = *(uint4*)v1;
        }
    }
    A_ISSUE(0);
    A_ISSUE(1);
    __syncthreads();

    unsigned qa[2][4][4];
    #pragma unroll
    for (int hq = 0; hq < 2; hq++) {
        const int qrow = hq * 128 + w * 16 + g;
        #pragma unroll
        for (int kk = 0; kk < 4; kk++) {
            qa[hq][kk][0] = *(const unsigned*)(Qs + qrow * KST + kk * 16 + 2 * t);
            qa[hq][kk][1] = *(const unsigned*)(Qs + (qrow + 8) * KST + kk * 16 + 2 * t);
            qa[hq][kk][2] = *(const unsigned*)(Qs + qrow * KST + kk * 16 + 8 + 2 * t);
            qa[hq][kk][3] = *(const unsigned*)(Qs + (qrow + 8) * KST + kk * 16 + 8 + 2 * t);
        }
    }

    float o[2][8][4] = {};
    float ol[2][4] = {};

    const int lrow = lane & 7;
    const int lh8  = ((lane >> 3) & 1) << 3;
    const int ln8  = (lane >> 4) << 3;
    const int vrow = lrow + lh8;
    const int vcol = ln8;

    for (int kt = 0; kt < 16; kt++) {
        if (kt + 1 < 16) cp_wait<1>(); else cp_wait<0>();
        __syncthreads();
        if (kt + 2 < 16) A_ISSUE(kt + 2);

        const unsigned Kb_ = smb + QS_SZ * 2 + (kt % 3) * BUF_BYTES;
        const unsigned Vb_ = Kb_ + KT_SZ * 2;

        #pragma unroll
        for (int hq = 0; hq < 2; hq++) {
            float s[16][4] = {};
            #pragma unroll
            for (int kk = 0; kk < 4; kk++) {
                #pragma unroll
                for (int nt2 = 0; nt2 < 8; nt2++) {
                    unsigned r0, r1, r2, r3;
                    unsigned addr = Kb_ +
                        (((nt2 * 16 + lrow + ln8) * KST) + kk * 16 + lh8) * 2;
                    ldmx4(r0, r1, r2, r3, addr);
                    mma16816(s[2 * nt2],     qa[hq][kk], r0, r1);
                    mma16816(s[2 * nt2 + 1], qa[hq][kk], r2, r3);
                }
            }

            unsigned aP[8][4];
            #pragma unroll
            for (int nt = 0; nt < 16; nt++) {
                unsigned sp01 = packh2(s[nt][0], s[nt][1]);
                unsigned sp23 = packh2(s[nt][2], s[nt][3]);
                int k2 = nt >> 1, off = (nt & 1) * 2;
                aP[k2][off]     = h2ex2(sp01);
                aP[k2][off + 1] = h2ex2(sp23);
            }

            #pragma unroll
            for (int kt2 = 0; kt2 < 8; kt2++) {
                #pragma unroll
                for (int nt2 = 0; nt2 < 4; nt2++) {
                    unsigned r0, r1, r2, r3;
                    unsigned addr = Vb_ +
                        (((kt2 * 16 + vrow) * VST) + nt2 * 16 + vcol) * 2;
                    ldmx4t(r0, r1, r2, r3, addr);
                    mma16816(o[hq][2 * nt2],     aP[kt2], r0, r1);
                    mma16816(o[hq][2 * nt2 + 1], aP[kt2], r2, r3);
                }
                unsigned r0, r1, r2, r3;
                unsigned addr = Vb_ +
                    (((kt2 * 16 + vrow) * VST) + 64 + vcol) * 2;
                ldmx4t(r0, r1, r2, r3, addr);
                mma16816(ol[hq], aP[kt2], r0, r1);
            }
        }
    }
#undef A_ISSUE

    #pragma unroll
    for (int hq = 0; hq < 2; hq++) {
        int qlead = lane & ~3;
        float l0 = __shfl_sync(0xffffffffu, ol[hq][0], qlead);
        float l1 = __shfl_sync(0xffffffffu, ol[hq][2], qlead);
        float inv0 = 1.f / l0, inv1 = 1.f / l1;
        size_t row0 = (size_t)bI * 2048 + qt * 256 + hq * 128 + w * 16 + g;
        #pragma unroll
        for (int nt = 0; nt < 8; nt++) {
            int col = h * 64 + nt * 8 + 2 * t;
            size_t o0 = row0 * DM + col;
            size_t o1 = (row0 + 8) * DM + col;
            *(__half2*)(g_O16 + o0) =
                __halves2half2(__float2half_rn(o[hq][nt][0] * inv0),
                               __float2half_rn(o[hq][nt][1] * inv0));
            *(__half2*)(g_O16 + o1) =
                __halves2half2(__float2half_rn(o[hq][nt][2] * inv1),
                               __float2half_rn(o[hq][nt][3] * inv1));
        }
    }
}

// ---------------- warp-per-row LayerNorm (no block barriers) ------------------
// 8 warps/block, each warp owns one row: 32 elems/thread, shfl-only reduction.
template <bool EMIT16>
__global__ __launch_bounds__(256) void ln_kernel(
    const float* __restrict__ y, const float* __restrict__ g,
    const float* __restrict__ bta, float* __restrict__ out,
    fp16* __restrict__ outh)
{
    const int lane = threadIdx.x & 31, wrp = threadIdx.x >> 5;
    const int row = blockIdx.x * 8 + wrp;
    const float* yr = y + (size_t)row * DM;

    float4 v[8];
    float a = 0.f, q = 0.f;
    #pragma unroll
    for (int i = 0; i < 8; i++) {
        v[i] = *(const float4*)(yr + lane * 4 + i * 128);
        a += v[i].x + v[i].y + v[i].z + v[i].w;
        q += v[i].x * v[i].x + v[i].y * v[i].y +
             v[i].z * v[i].z + v[i].w * v[i].w;
    }
    #pragma unroll
    for (int off = 16; off > 0; off >>= 1) {
        a += __shfl_xor_sync(0xffffffffu, a, off);
        q += __shfl_xor_sync(0xffffffffu, q, off);
    }
    const float mu = a * (1.f / DM);
    const float var = q * (1.f / DM) - mu * mu;
    const float rstd = rsqrtf(var + EPSLN);

    #pragma unroll
    for (int i = 0; i < 8; i++) {
        int c = lane * 4 + i * 128;
        float4 gv = *(const float4*)(g + c);
        float4 bv = *(const float4*)(bta + c);
        float4 ov;
        ov.x = (v[i].x - mu) * rstd * gv.x + bv.x;
        ov.y = (v[i].y - mu) * rstd * gv.y + bv.y;
        ov.z = (v[i].z - mu) * rstd * gv.z + bv.z;
        ov.w = (v[i].w - mu) * rstd * gv.w + bv.w;
        size_t o = (size_t)row * DM + c;
        *(float4*)(out + o) = ov;
        if (EMIT16) {
            __half2 h2[2];
            h2[0] = __floats2half2_rn(ov.x, ov.y);
            h2[1] = __floats2half2_rn(ov.z, ov.w);
            *(unsigned long long*)(outh + o) = *(unsigned long long*)h2;
        }
    }
}

// ---------------- launch ------------------------------------------------------
extern "C" void kernel_launch(void* const* d_in, const int* in_sizes, int n_in,
                              void* d_out, int out_size)
{
    const float* x   = (const float*)d_in[0];
    const float* Wq  = (const float*)d_in[1];
    const float* bq  = (const float*)d_in[2];
    const float* Wk  = (const float*)d_in[3];
    const float* bk  = (const float*)d_in[4];
    const float* Wv  = (const float*)d_in[5];
    const float* bv  = (const float*)d_in[6];
    const float* Wo  = (const float*)d_in[7];
    const float* g1  = (const float*)d_in[8];
    const float* be1 = (const float*)d_in[9];
    const float* W1  = (const float*)d_in[10];
    const float* b1f = (const float*)d_in[11];
    const float* W2  = (const float*)d_in[12];
    const float* g2  = (const float*)d_in[13];
    const float* be2 = (const float*)d_in[14];
    float* out = (float*)d_out;

    void *px16, *pWq, *pWo, *pW1, *pW2, *pbq, *pO, *py1, *ph1, *ph116, *pff, *py2;
    cudaGetSymbolAddress(&px16, g_x16);
    cudaGetSymbolAddress(&pWq, g_Wqkv);
    cudaGetSymbolAddress(&pWo, g_Wo16);
    cudaGetSymbolAddress(&pW1, g_W116);
    cudaGetSymbolAddress(&pW2, g_W216);
    cudaGetSymbolAddress(&pbq, g_bqkv);
    cudaGetSymbolAddress(&pO, g_O16);
    cudaGetSymbolAddress(&py1, g_y1);
    cudaGetSymbolAddress(&ph1, g_h1);
    cudaGetSymbolAddress(&ph116, g_h116);
    cudaGetSymbolAddress(&pff, g_ff16);
    cudaGetSymbolAddress(&py2, g_y2);

    cudaFuncSetAttribute(gemm1_kernel<0, 96>,
                         cudaFuncAttributeMaxDynamicSharedMemorySize, GCfg<96>::SMEM);
    cudaFuncSetAttribute(gemm1_kernel<1, 128>,
                         cudaFuncAttributeMaxDynamicSharedMemorySize, GCfg<128>::SMEM);
    cudaFuncSetAttribute(gemm1_kernel<2, 128>,
                         cudaFuncAttributeMaxDynamicSharedMemorySize, GCfg<128>::SMEM);
    cudaFuncSetAttribute(attn_kernel,
                         cudaFuncAttributeMaxDynamicSharedMemorySize, ATTN_SMEM);

    // ---- prep (single fused launch)
    prep_kernel<<<PREP_BLOCKS, 256>>>(x, Wq, Wk, Wv, bq, bk, bv, Wo, W1, W2);

    // ---- 1) QKV projection (BN=96)
    gemm1_kernel<0, 96><<<dim3(32, 32), 256, GCfg<96>::SMEM>>>(
        (const fp16*)px16, (const fp16*)pWq, (const float*)pbq,
        nullptr, nullptr, nullptr, 1024, 3072);

    // ---- 2) tensor-core flash attention
    attn_kernel<<<dim3(8, HEADS), 256, ATTN_SMEM>>>();

    // ---- 3) O-proj + residual x -> y1
    gemm1_kernel<1, 128><<<dim3(8, 32), 256, GCfg<128>::SMEM>>>(
        (const fp16*)pO, (const fp16*)pWo, nullptr, x, (float*)py1, nullptr,
        1024, 1024);

    // ---- 4) LayerNorm 1 (warp-per-row)
    ln_kernel<true><<<NROWS / 8, 256>>>((const float*)py1, g1, be1,
                                        (float*)ph1, (fp16*)ph116);

    // ---- 5) FFN up + bias + ReLU
    gemm1_kernel<2, 128><<<dim3(32, 32), 256, GCfg<128>::SMEM>>>(
        (const fp16*)ph116, (const fp16*)pW1, b1f, nullptr, nullptr, (fp16*)pff,
        1024, 4096);

    // ---- 6) FFN down + residual h1 -> y2
    gemm1_kernel<1, 128><<<dim3(8, 32), 256, GCfg<128>::SMEM>>>(
        (const fp16*)pff, (const fp16*)pW2, nullptr, (const float*)ph1,
        (float*)py2, nullptr, 4096, 1024);

    // ---- 7) LayerNorm 2 -> output (warp-per-row)
    ln_kernel<false><<<NROWS / 8, 256>>>((const float*)py2, g2, be2, out, nullptr);
}